// round 17
// baseline (speedup 1.0000x reference)
#include <cuda_runtime.h>
#include <cuda_fp16.h>
#include <cstddef>
#include <cstdint>

#define Bn   4
#define Nn   8192
#define Cn   512
#define DHn  128
#define GSPL 8

// ---------------- scratch (device globals) ---------------------------------
__device__ __align__(128) __half g_xh  [(size_t)Bn * Nn * Cn];
__device__ __align__(128) __half g_xt  [(size_t)Bn * Cn * Nn];
__device__ __align__(128) __half g_wqk2[1024 * 1024];
__device__ __align__(128) __half g_woh [512 * 512];
__device__ __align__(128) __half g_wvt [512 * 512];
__device__ __align__(128) float  g_gramP[(size_t)Bn * GSPL * 512 * 512];
__device__ __align__(128) __half g_g2  [Bn * 512 * 1024];
__device__ __align__(128) __half g_T1  [Bn * 1024 * 512];
__device__ __align__(128) float  g_diag[Bn * 1024];
__device__ __align__(128) float  g_qkP [4 * 16 * DHn * DHn];
__device__ __align__(128) __half g_attnT[16 * DHn * DHn];
__device__ __align__(128) __half g_M   [Bn * Cn * Cn];
__device__ __align__(128) __half g_P   [Bn * Cn * Cn];
__device__ int g_cntG[Bn * 10];    // zero-init; reset by finisher each run
__device__ int g_cntQ[16];

__device__ const int c_ti[10] = {0,0,0,0,1,1,1,2,2,3};
__device__ const int c_tj[10] = {0,1,2,3,1,2,3,2,3,3};

// ---------------- PTX helpers ----------------------------------------------
__device__ __forceinline__ uint32_t sptr(const void* p) {
    return (uint32_t)__cvta_generic_to_shared(p);
}
#define CPA(dst, src) asm volatile("cp.async.cg.shared.global [%0],[%1],16;\n" \
                                   :: "r"(dst), "l"(src))
#define CPC() asm volatile("cp.async.commit_group;\n")
#define CPW0() asm volatile("cp.async.wait_group 0;\n")
#define CPW1() asm volatile("cp.async.wait_group 1;\n")

__device__ __forceinline__ void ldmx4(uint32_t* r, uint32_t a) {
    asm volatile("ldmatrix.sync.aligned.m8n8.x4.shared.b16 {%0,%1,%2,%3},[%4];"
                 : "=r"(r[0]), "=r"(r[1]), "=r"(r[2]), "=r"(r[3]) : "r"(a));
}
__device__ __forceinline__ void mma16816(float* c, const uint32_t* a, const uint32_t* b) {
    asm volatile(
        "mma.sync.aligned.m16n8k16.row.col.f32.f16.f16.f32 "
        "{%0,%1,%2,%3},{%4,%5,%6,%7},{%8,%9},{%0,%1,%2,%3};"
        : "+f"(c[0]), "+f"(c[1]), "+f"(c[2]), "+f"(c[3])
        : "r"(a[0]), "r"(a[1]), "r"(a[2]), "r"(a[3]), "r"(b[0]), "r"(b[1]));
}

// ---------------------------------------------------------------------------
// Variant L256: 128x128 CTA tile, 256 threads = 8 warps of 32x64.
// BK=64, 2-stage ring. Stage: A 128x144B (+0), B 128x144B (+18432).
// ---------------------------------------------------------------------------
#define STAGE_BYTES 36864
#define BIG_SMEM    (2 * STAGE_BYTES)   // 73728

#define GEMM_MAINLOOP(A, B, K, lda, ldb, m0, n0)                               \
    const uint32_t s0 = sptr(dsm);                                             \
    const int tid  = threadIdx.x;                                              \
    const int lane = tid & 31;                                                 \
    const int wid  = tid >> 5;                                                 \
    const int wm   = (wid & 3) * 32;                                           \
    const int wn   = (wid >> 2) * 64;                                          \
    float acc[2][8][4];                                                        \
    _Pragma("unroll") for (int i = 0; i < 2; i++)                              \
    _Pragma("unroll") for (int j = 0; j < 8; j++)                              \
    _Pragma("unroll") for (int t = 0; t < 4; t++) acc[i][j][t] = 0.f;          \
    const int lrow = tid >> 3;           /* 0..31 */                           \
    const int lc16 = tid & 7;                                                  \
    const __half* Ag = (A) + (size_t)((m0) + lrow) * (lda) + lc16 * 8;         \
    const __half* Bg = (B) + (size_t)((n0) + lrow) * (ldb) + lc16 * 8;         \
    auto load_stage = [&](int stg, int k0) {                                   \
        const uint32_t ad = s0 + stg * STAGE_BYTES + lrow * 144 + lc16 * 16;   \
        const uint32_t bd = ad + 18432;                                        \
        _Pragma("unroll") for (int u = 0; u < 4; u++) {                        \
            CPA(ad + u * (32 * 144), Ag + (size_t)(u * 32) * (lda) + k0);      \
            CPA(bd + u * (32 * 144), Bg + (size_t)(u * 32) * (ldb) + k0);      \
        }                                                                      \
        CPC();                                                                 \
    };                                                                         \
    const uint32_t a_fb = (wm + (lane & 15)) * 144 + (lane >> 4) * 16;         \
    const uint32_t b_fb = 18432 +                                              \
        (wn + (lane & 7) + ((lane >> 4) * 8)) * 144 + ((lane >> 3) & 1) * 16;  \
    uint32_t af[2][2][4], bf[2][4][4];                                         \
    auto ldfrags = [&](int slot, int stg, int ks) {                            \
        const uint32_t ab = s0 + stg * STAGE_BYTES + a_fb + ks * 32;           \
        const uint32_t bb = s0 + stg * STAGE_BYTES + b_fb + ks * 32;           \
        _Pragma("unroll") for (int mi = 0; mi < 2; mi++)                       \
            ldmx4(af[slot][mi], ab + mi * (16 * 144));                         \
        _Pragma("unroll") for (int nj = 0; nj < 4; nj++)                       \
            ldmx4(bf[slot][nj], bb + nj * (16 * 144));                         \
    };                                                                         \
    auto mma_all = [&](int slot) {                                             \
        _Pragma("unroll") for (int mi = 0; mi < 2; mi++)                       \
        _Pragma("unroll") for (int nj = 0; nj < 8; nj++)                       \
            mma16816(acc[mi][nj], af[slot][mi], &bf[slot][nj >> 1][(nj & 1) * 2]); \
    };                                                                         \
    const int niter = (K) / 64;                                                \
    load_stage(0, 0);                                                          \
    load_stage(1, 64);                                                         \
    CPW1();                                                                    \
    __syncthreads();                                                           \
    ldfrags(0, 0, 0);                                                          \
    int st = 0;                                                                \
    for (int it = 0; it < niter; ++it) {                                       \
        ldfrags(1, st, 1); mma_all(0);                                         \
        ldfrags(0, st, 2); mma_all(1);                                         \
        ldfrags(1, st, 3); mma_all(0);                                         \
        if (it + 1 < niter) {                                                  \
            CPW0();                                                            \
            __syncthreads();                                                   \
            if (it + 2 < niter) load_stage(st, (it + 2) * 64);                 \
            ldfrags(0, st ^ 1, 0);                                             \
            st ^= 1;                                                           \
        }                                                                      \
        mma_all(1);                                                            \
    }

template<bool HALF_OUT, bool BIAS>
__device__ __forceinline__ void gemm_big(
    const __half* __restrict__ A, const __half* __restrict__ B,
    void* __restrict__ Cp, const float* __restrict__ bias,
    int K, int lda, int ldb, int ldc, int m0, int n0)
{
    extern __shared__ char dsm[];
    GEMM_MAINLOOP(A, B, K, lda, ldb, m0, n0)

    const int g  = lane >> 2;
    const int tg = lane & 3;
#pragma unroll
    for (int mi = 0; mi < 2; mi++) {
#pragma unroll
        for (int nj = 0; nj < 8; nj++) {
            const int r0 = m0 + wm + mi * 16 + g;
            const int cc = n0 + wn + nj * 8 + 2 * tg;
            float* a4 = acc[mi][nj];
            if (HALF_OUT) {
                __half* C = (__half*)Cp;
                *(__half2*)&C[(size_t)r0 * ldc + cc]       = __floats2half2_rn(a4[0], a4[1]);
                *(__half2*)&C[(size_t)(r0 + 8) * ldc + cc] = __floats2half2_rn(a4[2], a4[3]);
            } else {
                float* C = (float*)Cp;
                float b0 = 0.f, b1 = 0.f;
                if (BIAS) { float2 bb = *(const float2*)&bias[cc]; b0 = bb.x; b1 = bb.y; }
                *(float2*)&C[(size_t)r0 * ldc + cc]       = make_float2(a4[0] + b0, a4[1] + b1);
                *(float2*)&C[(size_t)(r0 + 8) * ldc + cc] = make_float2(a4[2] + b0, a4[3] + b1);
            }
        }
    }
}

// ---------------------------------------------------------------------------
// Variant S: 64x128 CTA tile (latency kernels)
// ---------------------------------------------------------------------------
#define STAGE_S  27648
#define SMEM_S   (2 * STAGE_S)   // 55296

#define GEMM_MAINLOOP_S(A, B, K, lda, ldb, m0, n0)                             \
    const uint32_t s0 = sptr(dsm);                                             \
    const int tid  = threadIdx.x;                                              \
    const int lane = tid & 31;                                                 \
    const int wid  = tid >> 5;                                                 \
    const int wn   = wid * 32;                                                 \
    float acc[4][4][4];                                                        \
    _Pragma("unroll") for (int i = 0; i < 4; i++)                              \
    _Pragma("unroll") for (int j = 0; j < 4; j++)                              \
    _Pragma("unroll") for (int t = 0; t < 4; t++) acc[i][j][t] = 0.f;          \
    const int lrow = tid >> 3;                                                 \
    const int lc16 = tid & 7;                                                  \
    const __half* Ag = (A) + (size_t)((m0) + lrow) * (lda) + lc16 * 8;         \
    const __half* Bg = (B) + (size_t)((n0) + lrow) * (ldb) + lc16 * 8;         \
    auto load_stage = [&](int stg, int k0) {                                   \
        const uint32_t ad = s0 + stg * STAGE_S + lrow * 144 + lc16 * 16;       \
        const uint32_t bd = ad + 9216;                                         \
        _Pragma("unroll") for (int u = 0; u < 4; u++)                          \
            CPA(ad + u * (16 * 144), Ag + (size_t)(u * 16) * (lda) + k0);      \
        _Pragma("unroll") for (int u = 0; u < 8; u++)                          \
            CPA(bd + u * (16 * 144), Bg + (size_t)(u * 16) * (ldb) + k0);      \
        CPC();                                                                 \
    };                                                                         \
    const uint32_t a_fb = (lane & 15) * 144 + (lane >> 4) * 16;                \
    const uint32_t b_fb = 9216 +                                               \
        (wn + (lane & 7) + ((lane >> 4) * 8)) * 144 + ((lane >> 3) & 1) * 16;  \
    uint32_t af[2][4][4], bf[2][2][4];                                         \
    auto ldfrags = [&](int slot, int stg, int ks) {                            \
        const uint32_t ab = s0 + stg * STAGE_S + a_fb + ks * 32;               \
        const uint32_t bb = s0 + stg * STAGE_S + b_fb + ks * 32;               \
        _Pragma("unroll") for (int mi = 0; mi < 4; mi++)                       \
            ldmx4(af[slot][mi], ab + mi * (16 * 144));                         \
        _Pragma("unroll") for (int nj = 0; nj < 2; nj++)                       \
            ldmx4(bf[slot][nj], bb + nj * (16 * 144));                         \
    };                                                                         \
    auto mma_all = [&](int slot) {                                             \
        _Pragma("unroll") for (int mi = 0; mi < 4; mi++)                       \
        _Pragma("unroll") for (int nj = 0; nj < 4; nj++)                       \
            mma16816(acc[mi][nj], af[slot][mi], &bf[slot][nj >> 1][(nj & 1) * 2]); \
    };                                                                         \
    const int niter = (K) / 64;                                                \
    load_stage(0, 0);                                                          \
    load_stage(1, 64);                                                         \
    CPW1();                                                                    \
    __syncthreads();                                                           \
    ldfrags(0, 0, 0);                                                          \
    int st = 0;                                                                \
    for (int it = 0; it < niter; ++it) {                                       \
        ldfrags(1, st, 1); mma_all(0);                                         \
        ldfrags(0, st, 2); mma_all(1);                                         \
        ldfrags(1, st, 3); mma_all(0);                                         \
        if (it + 1 < niter) {                                                  \
            CPW0();                                                            \
            __syncthreads();                                                   \
            if (it + 2 < niter) load_stage(st, (it + 2) * 64);                 \
            ldfrags(0, st ^ 1, 0);                                             \
            st ^= 1;                                                           \
        }                                                                      \
        mma_all(1);                                                            \
    }

template<bool HALF_OUT>
__device__ __forceinline__ void gemm_small(
    const __half* __restrict__ A, const __half* __restrict__ B,
    void* __restrict__ Cp,
    int K, int lda, int ldb, int ldc, int m0, int n0)
{
    extern __shared__ char dsm[];
    GEMM_MAINLOOP_S(A, B, K, lda, ldb, m0, n0)

    const int g  = lane >> 2;
    const int tg = lane & 3;
#pragma unroll
    for (int mi = 0; mi < 4; mi++) {
#pragma unroll
        for (int nj = 0; nj < 4; nj++) {
            const int r0 = m0 + mi * 16 + g;
            const int cc = n0 + wn + nj * 8 + 2 * tg;
            float* a4 = acc[mi][nj];
            if (HALF_OUT) {
                __half* C = (__half*)Cp;
                *(__half2*)&C[(size_t)r0 * ldc + cc]       = __floats2half2_rn(a4[0], a4[1]);
                *(__half2*)&C[(size_t)(r0 + 8) * ldc + cc] = __floats2half2_rn(a4[2], a4[3]);
            } else {
                float* C = (float*)Cp;
                *(float2*)&C[(size_t)r0 * ldc + cc]       = make_float2(a4[0], a4[1]);
                *(float2*)&C[(size_t)(r0 + 8) * ldc + cc] = make_float2(a4[2], a4[3]);
            }
        }
    }
}

// ---------------- GEMM kernels -----------------------------------------------
// 1. Gram partials + FUSED reduce (last CTA per (b,tile) reduces, mirrors,
//    hi/lo splits). grid (GSPL, 10, 4), 256 thr.
__global__ void __launch_bounds__(256, 2) k_gram()
{
    extern __shared__ char dsm[];
    const int b  = blockIdx.z;
    const int ti = c_ti[blockIdx.y], tj = c_tj[blockIdx.y];
    const int m0 = ti * 128, n0 = tj * 128;
    const __half* X = g_xt + (size_t)b * Cn * Nn + (size_t)blockIdx.x * (Nn / GSPL);

    GEMM_MAINLOOP(X, X, Nn / GSPL, Nn, Nn, m0, n0)

    // store fp32 partial
    {
        const int g  = lane >> 2;
        const int tg = lane & 3;
        float* C = g_gramP + ((size_t)b * GSPL + blockIdx.x) * 262144;
#pragma unroll
        for (int mi = 0; mi < 2; mi++)
#pragma unroll
            for (int nj = 0; nj < 8; nj++) {
                const int r0 = m0 + wm + mi * 16 + g;
                const int cc = n0 + wn + nj * 8 + 2 * tg;
                float* a4 = acc[mi][nj];
                *(float2*)&C[(size_t)r0 * 512 + cc]       = make_float2(a4[0], a4[1]);
                *(float2*)&C[(size_t)(r0 + 8) * 512 + cc] = make_float2(a4[2], a4[3]);
            }
    }
    __threadfence();
    __syncthreads();
    __shared__ int sdone;
    if (tid == 0) {
        const int old = atomicAdd(&g_cntG[b * 10 + blockIdx.y], 1);
        sdone = (old == GSPL - 1);
    }
    __syncthreads();
    if (!sdone) return;
    __threadfence();

    // last CTA: reduce 8 partials -> hi/lo, coalesced mirror via smem
    float* shm = (float*)dsm;          // 32x33 tile
    const float* gp = g_gramP + (size_t)b * GSPL * 262144;
    const int tx = tid & 31, ty8 = tid >> 5;   // 0..7
    for (int sub = 0; sub < 16; ++sub) {
        const int i0 = ti * 128 + (sub >> 2) * 32;
        const int j0 = tj * 128 + (sub & 3) * 32;
        __syncthreads();
#pragma unroll
        for (int r = 0; r < 4; r++) {
            const int i = i0 + ty8 + r * 8;
            const int j = j0 + tx;
            float s = 0.f;
#pragma unroll
            for (int p = 0; p < GSPL; p++)
                s += gp[(size_t)p * 262144 + i * 512 + j];
            const __half hi = __float2half_rn(s);
            g_g2[((size_t)b * 512 + i) * 1024 + j]       = hi;
            g_g2[((size_t)b * 512 + i) * 1024 + 512 + j] =
                __float2half_rn(s - __half2float(hi));
            shm[(ty8 + r * 8) * 33 + tx] = s;
        }
        if (ti != tj) {
            __syncthreads();
#pragma unroll
            for (int r = 0; r < 4; r++) {
                const int jj = j0 + ty8 + r * 8;
                const int ii = i0 + tx;
                const float s = shm[tx * 33 + ty8 + r * 8];
                const __half hi = __float2half_rn(s);
                g_g2[((size_t)b * 512 + jj) * 1024 + ii]       = hi;
                g_g2[((size_t)b * 512 + jj) * 1024 + 512 + ii] =
                    __float2half_rn(s - __half2float(hi));
            }
        }
    }
    if (tid == 0) g_cntG[b * 10 + blockIdx.y] = 0;   // reset for next replay
}

// 2. T1 = Wqk @ G (hi+lo), half out.  grid (4 nt, 16 mt, 4 b), S-variant.
__global__ void __launch_bounds__(128, 3) k_T1()
{
    const int b = blockIdx.z;
    const __half* Bg = g_g2 + (size_t)b * 512 * 1024;
    __half* C = g_T1 + (size_t)b * 1024 * 512;
    gemm_small<true>(g_wqk2, Bg, C, 1024, 1024, 1024, 512,
                     blockIdx.y * 64, blockIdx.x * 128);
}

// 3a. diag dots (warp per row)
__global__ void __launch_bounds__(256) kdiag()
{
    const int gw = blockIdx.x * 8 + (threadIdx.x >> 5);
    const int b = gw >> 10, r = gw & 1023;
    const int lane = threadIdx.x & 31;
    const __half2* t1 = (const __half2*)(g_T1 + ((size_t)b * 1024 + r) * 512);
    const __half2* wr = (const __half2*)(g_wqk2 + (size_t)r * 1024);
    float s = 0.f;
#pragma unroll
    for (int k = lane; k < 256; k += 32) {
        float2 a = __half22float2(t1[k]);
        float2 w = __half22float2(wr[k]);
        s = fmaf(a.x, w.x, fmaf(a.y, w.y, s));
    }
#pragma unroll
    for (int off = 16; off; off >>= 1)
        s += __shfl_xor_sync(0xffffffffu, s, off);
    if (lane == 0) g_diag[gw] = s;
}

// 3b. QK logits split-K partials + FUSED softmax (last CTA per bh).
//     grid (4 splits, 2 mt, 16 bh), S-mainloop, K=128. smem BIG (softmax buf).
__global__ void __launch_bounds__(128, 3) k_qkp(const float* __restrict__ temp)
{
    extern __shared__ char dsm[];
    const int s4 = blockIdx.x;
    const int mt = blockIdx.y;
    const int bh = blockIdx.z;
    const int b = bh >> 2, h = bh & 3;
    const __half* A = g_T1 + (size_t)b * 1024 * 512
                    + (size_t)(h * DHn + mt * 64) * 512 + s4 * 128;
    const __half* Bp = g_wqk2 + (size_t)(512 + h * DHn) * 1024 + s4 * 128;

    GEMM_MAINLOOP_S(A, Bp, 128, 512, 1024, 0, 0)

    // store fp32 partial
    {
        const int g  = lane >> 2;
        const int tg = lane & 3;
        float* C = g_qkP + ((size_t)s4 * 16 + bh) * (DHn * DHn) + mt * 64 * DHn;
#pragma unroll
        for (int mi = 0; mi < 4; mi++)
#pragma unroll
            for (int nj = 0; nj < 4; nj++) {
                const int r0 = mi * 16 + g;
                const int cc = wn + nj * 8 + 2 * tg;
                float* a4 = acc[mi][nj];
                *(float2*)&C[(size_t)r0 * DHn + cc]       = make_float2(a4[0], a4[1]);
                *(float2*)&C[(size_t)(r0 + 8) * DHn + cc] = make_float2(a4[2], a4[3]);
            }
    }
    __threadfence();
    __syncthreads();
    __shared__ int sdone;
    if (tid == 0) {
        const int old = atomicAdd(&g_cntQ[bh], 1);
        sdone = (old == 7);
    }
    __syncthreads();
    if (!sdone) return;
    __threadfence();

    // last CTA: sum partials + normalize + softmax over d; writes attnT[d][c]
    float* buf = (float*)dsm;                     // [128][129]
    float* sqv = buf + 128 * 129;                 // qinv*temp per c
    float* skv = sqv + 128;                       // kinv per d
    {
        const float qq = g_diag[b * 1024 + h * DHn + tid];
        const float kk = g_diag[b * 1024 + 512 + h * DHn + tid];
        sqv[tid] = temp[h] / fmaxf(sqrtf(fmaxf(qq, 0.f)), 1e-12f);
        skv[tid] = 1.f / fmaxf(sqrtf(fmaxf(kk, 0.f)), 1e-12f);
    }
    for (int idx = tid; idx < DHn * DHn; idx += 128) {
        float s = 0.f;
#pragma unroll
        for (int p = 0; p < 4; p++)
            s += g_qkP[((size_t)p * 16 + bh) * (DHn * DHn) + idx];
        buf[(idx >> 7) * 129 + (idx & 127)] = s;
    }
    __syncthreads();

    const int c = tid;
    const float qs = sqv[c];
    float mx = -1e30f;
#pragma unroll 8
    for (int d = 0; d < 128; d++)
        mx = fmaxf(mx, qs * (buf[c * 129 + d] * skv[d]));
    float sum = 0.f;
#pragma unroll 8
    for (int d = 0; d < 128; d++) {
        const float e = expf(qs * (buf[c * 129 + d] * skv[d]) - mx);
        buf[c * 129 + d] = e;
        sum += e;
    }
    const float inv = 1.f / sum;
    __half* dst = g_attnT + (size_t)bh * (DHn * DHn) + c;
#pragma unroll 8
    for (int d = 0; d < 128; d++)
        dst[d * DHn] = __float2half_rn(buf[c * 129 + d] * inv);

    if (tid == 0) g_cntQ[bh] = 0;   // reset for next replay
}

// 5. M_b[j][h*128+d] = Wout_h @ attn_bh   grid (1, 8 mt, 16 bh), S, K=128
__global__ void __launch_bounds__(128, 3) k_M()
{
    const int bh = blockIdx.z;
    const int b = bh >> 2, h = bh & 3;
    const __half* A  = g_woh + h * DHn;
    const __half* Bt = g_attnT + (size_t)bh * DHn * DHn;
    __half* C = g_M + (size_t)b * Cn * Cn + h * DHn;
    gemm_small<true>(A, Bt, C, DHn, 512, DHn, Cn, blockIdx.y * 64, 0);
}

// 6. P_b = M_b @ Wv, half out. grid (4 nt, 8 mt, 4 b), S, K=512
__global__ void __launch_bounds__(128, 3) k_P()
{
    const int b = blockIdx.z;
    const __half* A = g_M + (size_t)b * Cn * Cn;
    __half* C = g_P + (size_t)b * Cn * Cn;
    gemm_small<true>(A, g_wvt, C, 512, 512, 512, 512,
                     blockIdx.y * 64, blockIdx.x * 128);
}

// 7. out = x @ P^T + bias   grid (4, 64, 4), L256-variant
__global__ void __launch_bounds__(256, 2) k_out(float* __restrict__ out,
                                                const float* __restrict__ bias)
{
    const int b = blockIdx.z;
    const __half* A = g_xh + (size_t)b * Nn * Cn;
    const __half* Bp = g_P + (size_t)b * Cn * Cn;
    float* C = out + (size_t)b * Nn * Cn;
    gemm_big<false, true>(A, Bp, C, bias, 512, 512, 512, 512,
                          blockIdx.y * 128, blockIdx.x * 128);
}

// ---------------- small kernels ---------------------------------------------
__global__ void __launch_bounds__(256) xprep(const float* __restrict__ x)
{
    __shared__ __half ts[32][33];
    const int n0 = blockIdx.x * 32, c0 = blockIdx.y * 32, b = blockIdx.z;
    const int tx = threadIdx.x, ty = threadIdx.y;
#pragma unroll
    for (int r = 0; r < 4; r++) {
        const size_t idx = ((size_t)b * Nn + n0 + ty + r * 8) * Cn + c0 + tx;
        const __half hv = __float2half_rn(x[idx]);
        g_xh[idx] = hv;
        ts[ty + r * 8][tx] = hv;
    }
    __syncthreads();
#pragma unroll
    for (int r = 0; r < 4; r++)
        g_xt[((size_t)b * Cn + c0 + ty + r * 8) * Nn + n0 + tx] = ts[tx][ty + r * 8];
}

__global__ void __launch_bounds__(256) wprep(const float* __restrict__ Wqkv,
                                             const float* __restrict__ Wout)
{
    const int idx = blockIdx.x * 256 + threadIdx.x;
    if (idx < 1024 * 1024) {
        const int m = idx >> 10, k = idx & 1023;
        g_wqk2[idx] = __float2half_rn(Wqkv[m * 512 + (k & 511)]);
    } else if (idx < 1024 * 1024 + 262144) {
        const int t = idx - 1024 * 1024;
        g_woh[t] = __float2half_rn(Wout[t]);
    } else {
        const int t = idx - 1024 * 1024 - 262144;
        const int j = t >> 9, m = t & 511;
        g_wvt[t] = __float2half_rn(Wqkv[(1024 + m) * 512 + j]);
    }
}

// ---------------------------------------------------------------------------
extern "C" void kernel_launch(void* const* d_in, const int* in_sizes, int n_in,
                              void* d_out, int out_size)
{
    const float* x    = (const float*)d_in[0];
    const float* Wqkv = (const float*)d_in[1];
    const float* Wout = (const float*)d_in[2];
    const float* bout = (const float*)d_in[3];
    const float* temp = (const float*)d_in[4];
    float* out = (float*)d_out;

    cudaFuncSetAttribute(k_gram, cudaFuncAttributeMaxDynamicSharedMemorySize, BIG_SMEM);
    cudaFuncSetAttribute(k_out,  cudaFuncAttributeMaxDynamicSharedMemorySize, BIG_SMEM);
    cudaFuncSetAttribute(k_T1,   cudaFuncAttributeMaxDynamicSharedMemorySize, SMEM_S);
    cudaFuncSetAttribute(k_qkp,  cudaFuncAttributeMaxDynamicSharedMemorySize, BIG_SMEM);
    cudaFuncSetAttribute(k_M,    cudaFuncAttributeMaxDynamicSharedMemorySize, SMEM_S);
    cudaFuncSetAttribute(k_P,    cudaFuncAttributeMaxDynamicSharedMemorySize, SMEM_S);

    // 0. conversions / layouts
    xprep<<<dim3(Nn / 32, Cn / 32, Bn), dim3(32, 8)>>>(x);
    wprep<<<6144, 256>>>(Wqkv, Wout);

    // 1. Gram partials + fused reduce/mirror/split
    k_gram<<<dim3(GSPL, 10, Bn), 256, BIG_SMEM>>>();

    // 2. T1 = Wqk @ G (hi+lo), latency-shaped
    k_T1<<<dim3(4, 16, Bn), 128, SMEM_S>>>();

    // 3. diagonal norms, then split-K logits + fused softmax
    kdiag<<<512, 256>>>();
    k_qkp<<<dim3(4, 2, 16), 128, BIG_SMEM>>>(temp);

    // 5. M = Wout_h @ attn_h
    k_M<<<dim3(1, 8, 16), 128, SMEM_S>>>();

    // 6. P = M @ Wv
    k_P<<<dim3(4, 8, Bn), 128, SMEM_S>>>();

    // 7. out = x @ P^T + bias
    k_out<<<dim3(4, 64, Bn), 256, BIG_SMEM>>>(out, bout);
}